// round 5
// baseline (speedup 1.0000x reference)
#include <cuda_runtime.h>
#include <cuda_bf16.h>

// GCN: 3x (h = relu(A_norm @ (h @ W) + b)) -> global mean pool -> MLP.
// CSR-by-dst per launch. 9 launches total:
//   hist, scanA(+ticket-fused block-sum scan), scanC(rowptr+dinv, re-zeroes
//   deg/fill for next replay), scatter, gemm1, agg+gemm2, agg+gemm3,
//   agg3(final), pool+mlp.
// Aggregation is gather-only (no float atomics); hW buffers (12.8MB) stay
// L2-resident. Layer GEMMs 2/3 are fused into the aggregate epilogue
// (activation row lives in warp registers), saving launches + g_h traffic.

#define NMAX 50000
#define EMAX 800000
#define GMAX 2048
#define SCAN_B 1024
#define NB_MAX 64

__device__ float g_hWa[NMAX * 64];     // ping
__device__ float g_hWb[NMAX * 64];     // pong
__device__ float g_h[NMAX * 64];       // final layer activations (for pool)
__device__ float g_dinv[NMAX];         // 1/sqrt(deg+1)
__device__ int   g_deg[NMAX];          // in-degree histogram (zeroed each run)
__device__ int   g_rowptr[NMAX + 1];   // CSR row pointers (by dst)
__device__ int   g_fill[NMAX];         // scatter cursors (zeroed each run)
__device__ int2  g_edges[EMAX];        // packed {src, __float_as_int(norm)}
__device__ int   g_bsum[NB_MAX];       // scan block sums -> exclusive prefixes
__device__ int   g_ticket;             // scanA completion ticket (self-reset)

// ---------------------------------------------------------------------------
// Histogram of dst, 4 edges per thread. Relies on g_deg zeroed (BSS on first
// call, re-zeroed by scanC on every call).
__global__ void hist_kernel(const int* __restrict__ ei, int E) {
    int base = (blockIdx.x * blockDim.x + threadIdx.x) * 4;
    if ((E & 3) == 0) {
        if (base < E) {
            int4 d = *reinterpret_cast<const int4*>(ei + E + base);
            atomicAdd(&g_deg[d.x], 1);
            atomicAdd(&g_deg[d.y], 1);
            atomicAdd(&g_deg[d.z], 1);
            atomicAdd(&g_deg[d.w], 1);
        }
    } else {
#pragma unroll
        for (int j = 0; j < 4; j++)
            if (base + j < E) atomicAdd(&g_deg[ei[E + base + j]], 1);
    }
}

// scanA: per-block reduce -> g_bsum; last block to finish exclusively scans
// the <=NB_MAX block sums in-place and resets the ticket.
__global__ void scanA_kernel(int n, int nb) {
    __shared__ int ws[32];
    const int lane = threadIdx.x & 31, wid = threadIdx.x >> 5;
    int idx = blockIdx.x * SCAN_B + threadIdx.x;
    int v = (idx < n) ? g_deg[idx] : 0;
#pragma unroll
    for (int off = 16; off; off >>= 1) v += __shfl_down_sync(0xffffffffu, v, off);
    if (lane == 0) ws[wid] = v;
    __syncthreads();
    if (threadIdx.x == 0) {
        int s = 0;
#pragma unroll
        for (int w = 0; w < SCAN_B / 32; w++) s += ws[w];
        g_bsum[blockIdx.x] = s;
        __threadfence();
        int t = atomicAdd(&g_ticket, 1);
        if (t == nb - 1) {                 // last block: scan sums serially
            int run = 0;
            for (int j = 0; j < nb; j++) {
                int bv = g_bsum[j];
                g_bsum[j] = run;
                run += bv;
            }
            __threadfence();
            g_ticket = 0;                  // reset for next replay
        }
    }
}

// scanC: local rescan + block offset -> rowptr; dinv; re-zero deg & fill.
__global__ void scanC_kernel(int n) {
    __shared__ int ws[32];
    const int lane = threadIdx.x & 31, wid = threadIdx.x >> 5;
    int idx = blockIdx.x * SCAN_B + threadIdx.x;
    int v = (idx < n) ? g_deg[idx] : 0;
    int sc = v;
#pragma unroll
    for (int off = 1; off < 32; off <<= 1) {
        int u = __shfl_up_sync(0xffffffffu, sc, off);
        if (lane >= off) sc += u;
    }
    if (lane == 31) ws[wid] = sc;
    __syncthreads();
    if (wid == 0) {
        int s = ws[lane];
#pragma unroll
        for (int off = 1; off < 32; off <<= 1) {
            int u = __shfl_up_sync(0xffffffffu, s, off);
            if (lane >= off) s += u;
        }
        ws[lane] = s;
    }
    __syncthreads();
    int off = g_bsum[blockIdx.x] + (wid ? ws[wid - 1] : 0);
    int ex = off + sc - v;
    if (idx < n) {
        g_rowptr[idx] = ex;
        g_dinv[idx] = rsqrtf((float)(v + 1));   // +1 self loop
        g_deg[idx] = 0;                          // ready for next replay
        g_fill[idx] = 0;                         // ready for scatter
        if (idx == n - 1) g_rowptr[n] = ex + v;
    }
}

// Scatter edges into CSR slots, 4 edges per thread.
__global__ void scatter_kernel(const int* __restrict__ ei, int E) {
    int base = (blockIdx.x * blockDim.x + threadIdx.x) * 4;
    if ((E & 3) == 0) {
        if (base < E) {
            int4 s4 = *reinterpret_cast<const int4*>(ei + base);
            int4 d4 = *reinterpret_cast<const int4*>(ei + E + base);
            int ss[4] = {s4.x, s4.y, s4.z, s4.w};
            int dd[4] = {d4.x, d4.y, d4.z, d4.w};
#pragma unroll
            for (int j = 0; j < 4; j++) {
                float w = g_dinv[ss[j]] * g_dinv[dd[j]];
                int pos = g_rowptr[dd[j]] + atomicAdd(&g_fill[dd[j]], 1);
                g_edges[pos] = make_int2(ss[j], __float_as_int(w));
            }
        }
    } else {
#pragma unroll
        for (int j = 0; j < 4; j++) {
            if (base + j < E) {
                int s = ei[base + j], d = ei[E + base + j];
                float w = g_dinv[s] * g_dinv[d];
                int pos = g_rowptr[d] + atomicAdd(&g_fill[d], 1);
                g_edges[pos] = make_int2(s, __float_as_int(w));
            }
        }
    }
}

// ---------------------------------------------------------------------------
// Layer-1 GEMM: g_hWa[n,64] = X[n,32] @ W1[32,64]. Warp-per-row, W in SMEM.
__global__ void gemm1_kernel(const float* __restrict__ X,
                             const float* __restrict__ W, int n) {
    __shared__ float Ws[32 * 64];
    for (int i = threadIdx.x; i < 32 * 64; i += blockDim.x) Ws[i] = W[i];
    __syncthreads();
    const int lane = threadIdx.x & 31;
    const int warp = (blockIdx.x * blockDim.x + threadIdx.x) >> 5;
    const int nwarps = (gridDim.x * blockDim.x) >> 5;
    for (int row = warp; row < n; row += nwarps) {
        float x0 = X[(size_t)row * 32 + lane];
        float a0 = 0.f, a1 = 0.f;
#pragma unroll
        for (int k = 0; k < 32; k++) {
            float xv = __shfl_sync(0xffffffffu, x0, k);
            a0 += xv * Ws[k * 64 + lane];
            a1 += xv * Ws[k * 64 + 32 + lane];
        }
        g_hWa[(size_t)row * 64 + lane] = a0;
        g_hWa[(size_t)row * 64 + 32 + lane] = a1;
    }
}

// ---------------------------------------------------------------------------
// Warp-level edge aggregation into (a0, a1): gathers from IN, 4-deep unroll.
__device__ __forceinline__ void warp_aggregate(const float* __restrict__ IN,
                                               int node, int lane,
                                               float& a0, float& a1) {
    float dn = g_dinv[node];
    float self = dn * dn;
    a0 = self * IN[(size_t)node * 64 + lane];
    a1 = self * IN[(size_t)node * 64 + 32 + lane];
    int p = g_rowptr[node];
    const int e = g_rowptr[node + 1];
    const int m = p + ((e - p) & ~3);
    for (; p < m; p += 4) {
        int2 r0 = g_edges[p];
        int2 r1 = g_edges[p + 1];
        int2 r2 = g_edges[p + 2];
        int2 r3 = g_edges[p + 3];
        const float* s0 = IN + (size_t)r0.x * 64;
        const float* s1 = IN + (size_t)r1.x * 64;
        const float* s2 = IN + (size_t)r2.x * 64;
        const float* s3 = IN + (size_t)r3.x * 64;
        float v00 = s0[lane], v01 = s0[32 + lane];
        float v10 = s1[lane], v11 = s1[32 + lane];
        float v20 = s2[lane], v21 = s2[32 + lane];
        float v30 = s3[lane], v31 = s3[32 + lane];
        float w0 = __int_as_float(r0.y), w1 = __int_as_float(r1.y);
        float w2 = __int_as_float(r2.y), w3 = __int_as_float(r3.y);
        a0 += w0 * v00; a1 += w0 * v01;
        a0 += w1 * v10; a1 += w1 * v11;
        a0 += w2 * v20; a1 += w2 * v21;
        a0 += w3 * v30; a1 += w3 * v31;
    }
    for (; p < e; p++) {
        int2 r = g_edges[p];
        float w = __int_as_float(r.y);
        const float* s = IN + (size_t)r.x * 64;
        a0 += w * s[lane];
        a1 += w * s[32 + lane];
    }
}

// Aggregate(IN) -> act = relu(. + b) -> OUT = act @ W (fused next-layer GEMM).
// IN/OUT selected by template to keep __device__ globals directly addressed.
template <int IN_A>   // 1: IN=g_hWa, OUT=g_hWb ; 0: IN=g_hWb, OUT=g_hWa
__global__ void agg_gemm_kernel(const float* __restrict__ b,
                                const float* __restrict__ W, int n) {
    __shared__ float Ws[64 * 64];
    for (int i = threadIdx.x; i < 64 * 64; i += blockDim.x) Ws[i] = W[i];
    __syncthreads();
    const float* IN = IN_A ? g_hWa : g_hWb;
    float* OUT = IN_A ? g_hWb : g_hWa;
    const int lane = threadIdx.x & 31;
    const int warp = (blockIdx.x * blockDim.x + threadIdx.x) >> 5;
    const int nwarps = (gridDim.x * blockDim.x) >> 5;
    float bb0 = b[lane], bb1 = b[32 + lane];
    for (int node = warp; node < n; node += nwarps) {
        float a0, a1;
        warp_aggregate(IN, node, lane, a0, a1);
        a0 = fmaxf(a0 + bb0, 0.f);
        a1 = fmaxf(a1 + bb1, 0.f);
        // fused GEMM: row(64) @ W(64x64)
        float o0 = 0.f, o1 = 0.f;
#pragma unroll
        for (int k = 0; k < 32; k++) {
            float xv = __shfl_sync(0xffffffffu, a0, k);
            o0 += xv * Ws[k * 64 + lane];
            o1 += xv * Ws[k * 64 + 32 + lane];
        }
#pragma unroll
        for (int k = 0; k < 32; k++) {
            float xv = __shfl_sync(0xffffffffu, a1, k);
            o0 += xv * Ws[(k + 32) * 64 + lane];
            o1 += xv * Ws[(k + 32) * 64 + 32 + lane];
        }
        OUT[(size_t)node * 64 + lane] = o0;
        OUT[(size_t)node * 64 + 32 + lane] = o1;
    }
}

// Final aggregate (layer 3): act -> g_h (no trailing GEMM).
__global__ void agg_final_kernel(const float* __restrict__ b, int n) {
    const int lane = threadIdx.x & 31;
    const int warp = (blockIdx.x * blockDim.x + threadIdx.x) >> 5;
    const int nwarps = (gridDim.x * blockDim.x) >> 5;
    float bb0 = b[lane], bb1 = b[32 + lane];
    for (int node = warp; node < n; node += nwarps) {
        float a0, a1;
        warp_aggregate(g_hWa, node, lane, a0, a1);
        g_h[(size_t)node * 64 + lane] = fmaxf(a0 + bb0, 0.f);
        g_h[(size_t)node * 64 + 32 + lane] = fmaxf(a1 + bb1, 0.f);
    }
}

// ---------------------------------------------------------------------------
__device__ __forceinline__ int lbound(const int* __restrict__ a, int n, int v) {
    int lo = 0, hi = n;
    while (lo < hi) {
        int m = (lo + hi) >> 1;
        if (a[m] < v) lo = m + 1; else hi = m;
    }
    return lo;
}

// Fused mean-pool + MLP head. One warp per graph (batch ids sorted).
__global__ void pool_mlp_kernel(const int* __restrict__ batch,
                                const float* __restrict__ lw1,
                                const float* __restrict__ lb1,
                                const float* __restrict__ lw2,
                                const float* __restrict__ lb2,
                                float* __restrict__ out, int n, int G) {
    const int lane = threadIdx.x & 31;
    const int g = (blockIdx.x * blockDim.x + threadIdx.x) >> 5;
    if (g >= G) return;
    int start = lbound(batch, n, g);
    int end   = lbound(batch, n, g + 1);
    float p0 = 0.f, p1 = 0.f;
    for (int i = start; i < end; i++) {
        p0 += g_h[(size_t)i * 64 + lane];
        p1 += g_h[(size_t)i * 64 + 32 + lane];
    }
    int cnt = end - start;
    float inv = 1.f / (float)(cnt > 0 ? cnt : 1);
    p0 *= inv; p1 *= inv;

    float a0 = lb1[lane], a1 = lb1[32 + lane];
#pragma unroll
    for (int k = 0; k < 32; k++) {
        float xv = __shfl_sync(0xffffffffu, p0, k);
        a0 += xv * lw1[k * 64 + lane];
        a1 += xv * lw1[k * 64 + 32 + lane];
    }
#pragma unroll
    for (int k = 0; k < 32; k++) {
        float xv = __shfl_sync(0xffffffffu, p1, k);
        a0 += xv * lw1[(k + 32) * 64 + lane];
        a1 += xv * lw1[(k + 32) * 64 + 32 + lane];
    }
    a0 = fmaxf(a0, 0.f);
    a1 = fmaxf(a1, 0.f);
    float o0 = a0 * lw2[lane * 2 + 0] + a1 * lw2[(lane + 32) * 2 + 0];
    float o1 = a0 * lw2[lane * 2 + 1] + a1 * lw2[(lane + 32) * 2 + 1];
#pragma unroll
    for (int off = 16; off; off >>= 1) {
        o0 += __shfl_down_sync(0xffffffffu, o0, off);
        o1 += __shfl_down_sync(0xffffffffu, o1, off);
    }
    if (lane == 0) {
        out[g * 2 + 0] = o0 + lb2[0];
        out[g * 2 + 1] = o1 + lb2[1];
    }
}

// ---------------------------------------------------------------------------
extern "C" void kernel_launch(void* const* d_in, const int* in_sizes, int n_in,
                              void* d_out, int out_size) {
    const float* x     = (const float*)d_in[0];
    const int*   ei    = (const int*)d_in[1];    // int64 ref -> int32 device
    const int*   batch = (const int*)d_in[2];
    const float* W1 = (const float*)d_in[3];
    const float* b1 = (const float*)d_in[4];
    const float* W2 = (const float*)d_in[5];
    const float* b2 = (const float*)d_in[6];
    const float* W3 = (const float*)d_in[7];
    const float* b3 = (const float*)d_in[8];
    const float* lw1 = (const float*)d_in[9];
    const float* lb1 = (const float*)d_in[10];
    const float* lw2 = (const float*)d_in[11];
    const float* lb2 = (const float*)d_in[12];
    float* out = (float*)d_out;

    const int N = in_sizes[0] / 32;
    const int E = in_sizes[1] / 2;
    const int G = out_size / 2;

    const int T = 256;
    const int nb = (N + SCAN_B - 1) / SCAN_B;   // <= NB_MAX
    const int e4 = (E + 3) / 4;

    // --- CSR build (4 launches) ---
    hist_kernel<<<(e4 + T - 1) / T, T>>>(ei, E);
    scanA_kernel<<<nb, SCAN_B>>>(N, nb);
    scanC_kernel<<<nb, SCAN_B>>>(N);
    scatter_kernel<<<(e4 + T - 1) / T, T>>>(ei, E);

    const int work_blocks = 592;  // 4 blocks/SM, persistent-style loops

    // --- Layers (4 launches) ---
    gemm1_kernel<<<work_blocks, T>>>(x, W1, N);          // x@W1 -> A
    agg_gemm_kernel<1><<<work_blocks, T>>>(b1, W2, N);   // agg(A)+b1,relu @W2 -> B
    agg_gemm_kernel<0><<<work_blocks, T>>>(b2, W3, N);   // agg(B)+b2,relu @W3 -> A
    agg_final_kernel<<<work_blocks, T>>>(b3, N);         // agg(A)+b3,relu -> g_h

    // --- Fused pool + MLP head (1 launch) ---
    pool_mlp_kernel<<<(G * 32 + T - 1) / T, T>>>(batch, lw1, lb1, lw2, lb2,
                                                 out, N, G);
}

// round 6
// speedup vs baseline: 1.0713x; 1.0713x over previous
#include <cuda_runtime.h>
#include <cuda_bf16.h>

// GCN: 3x (h = relu(A_norm @ (h @ W) + b)) -> global mean pool -> MLP.
// 11 launches: hist, scanA(+ticket block-sum scan), scanC(rowptr+dinv+fill,
// re-zero deg), scatter(short chain: atomic cursor only), gemm1+norm-fill,
// [agg, gemm]x2, agg3, pool+mlp.
// Aggregation is gather-only (no float atomics); hW (12.8MB) stays
// L2-resident. Separate gemm/agg kernels (fusing them regressed: GEMM shfl
// chain starves the gather-loop MLP).

#define NMAX 50000
#define EMAX 800000
#define GMAX 2048
#define SCAN_B 1024
#define NB_MAX 64

__device__ float g_hW[NMAX * 64];      // X @ W scratch (GEMM out, agg in)
__device__ float g_h[NMAX * 64];       // activations (agg out, GEMM in)
__device__ float g_dinv[NMAX];         // 1/sqrt(deg+1)
__device__ int   g_deg[NMAX];          // histogram (re-zeroed every run)
__device__ int   g_rowptr[NMAX + 1];   // CSR row pointers (by dst)
__device__ int   g_fill[NMAX];         // scatter cursors, init = rowptr
__device__ int   g_esrc[EMAX];         // CSR edge sources
__device__ float g_enorm[EMAX];        // CSR edge norms dinv[s]*dinv[d]
__device__ int   g_bsum[NB_MAX];       // scan block sums -> excl prefixes
__device__ int   g_ticket;             // scanA ticket (self-resetting)

// ---------------------------------------------------------------------------
// Histogram of dst, 4 edges per thread (int4). g_deg zeroed by scanC/BSS.
__global__ void hist_kernel(const int* __restrict__ ei, int E) {
    int base = (blockIdx.x * blockDim.x + threadIdx.x) * 4;
    if ((E & 3) == 0) {
        if (base < E) {
            int4 d = *reinterpret_cast<const int4*>(ei + E + base);
            atomicAdd(&g_deg[d.x], 1);
            atomicAdd(&g_deg[d.y], 1);
            atomicAdd(&g_deg[d.z], 1);
            atomicAdd(&g_deg[d.w], 1);
        }
    } else {
#pragma unroll
        for (int j = 0; j < 4; j++)
            if (base + j < E) atomicAdd(&g_deg[ei[E + base + j]], 1);
    }
}

// scanA: per-block reduce -> g_bsum; last-finishing block scans the <=NB_MAX
// sums in place and resets the ticket.
__global__ void scanA_kernel(int n, int nb) {
    __shared__ int ws[32];
    const int lane = threadIdx.x & 31, wid = threadIdx.x >> 5;
    int idx = blockIdx.x * SCAN_B + threadIdx.x;
    int v = (idx < n) ? g_deg[idx] : 0;
#pragma unroll
    for (int off = 16; off; off >>= 1) v += __shfl_down_sync(0xffffffffu, v, off);
    if (lane == 0) ws[wid] = v;
    __syncthreads();
    if (threadIdx.x == 0) {
        int s = 0;
#pragma unroll
        for (int w = 0; w < SCAN_B / 32; w++) s += ws[w];
        g_bsum[blockIdx.x] = s;
        __threadfence();
        int t = atomicAdd(&g_ticket, 1);
        if (t == nb - 1) {
            int run = 0;
            for (int j = 0; j < nb; j++) {
                int bv = g_bsum[j];
                g_bsum[j] = run;
                run += bv;
            }
            __threadfence();
            g_ticket = 0;
        }
    }
}

// scanC: local rescan + block offset -> rowptr; fill=rowptr; dinv; zero deg.
__global__ void scanC_kernel(int n) {
    __shared__ int ws[32];
    const int lane = threadIdx.x & 31, wid = threadIdx.x >> 5;
    int idx = blockIdx.x * SCAN_B + threadIdx.x;
    int v = (idx < n) ? g_deg[idx] : 0;
    int sc = v;
#pragma unroll
    for (int off = 1; off < 32; off <<= 1) {
        int u = __shfl_up_sync(0xffffffffu, sc, off);
        if (lane >= off) sc += u;
    }
    if (lane == 31) ws[wid] = sc;
    __syncthreads();
    if (wid == 0) {
        int s = ws[lane];
#pragma unroll
        for (int off = 1; off < 32; off <<= 1) {
            int u = __shfl_up_sync(0xffffffffu, s, off);
            if (lane >= off) s += u;
        }
        ws[lane] = s;
    }
    __syncthreads();
    int off = g_bsum[blockIdx.x] + (wid ? ws[wid - 1] : 0);
    int ex = off + sc - v;
    if (idx < n) {
        g_rowptr[idx] = ex;
        g_fill[idx] = ex;                       // scatter cursor starts here
        g_dinv[idx] = rsqrtf((float)(v + 1));   // +1 self loop
        g_deg[idx] = 0;                          // ready for next replay
        if (idx == n - 1) g_rowptr[n] = ex + v;
    }
}

// Scatter: per edge just one atomic cursor bump + one 4B store.
__global__ void scatter_kernel(const int* __restrict__ ei, int E) {
    int base = (blockIdx.x * blockDim.x + threadIdx.x) * 4;
    if ((E & 3) == 0) {
        if (base < E) {
            int4 s4 = *reinterpret_cast<const int4*>(ei + base);
            int4 d4 = *reinterpret_cast<const int4*>(ei + E + base);
            g_esrc[atomicAdd(&g_fill[d4.x], 1)] = s4.x;
            g_esrc[atomicAdd(&g_fill[d4.y], 1)] = s4.y;
            g_esrc[atomicAdd(&g_fill[d4.z], 1)] = s4.z;
            g_esrc[atomicAdd(&g_fill[d4.w], 1)] = s4.w;
        }
    } else {
#pragma unroll
        for (int j = 0; j < 4; j++) {
            if (base + j < E) {
                int s = ei[base + j], d = ei[E + base + j];
                g_esrc[atomicAdd(&g_fill[d], 1)] = s;
            }
        }
    }
}

// ---------------------------------------------------------------------------
// Layer-1 GEMM (x[n,32] @ W1[32,64] -> g_hW) + edge norm fill (independent).
__global__ void gemm1_norm_kernel(const float* __restrict__ X,
                                  const float* __restrict__ W, int n) {
    __shared__ float Ws[32 * 64];
    for (int i = threadIdx.x; i < 32 * 64; i += blockDim.x) Ws[i] = W[i];
    __syncthreads();
    const int lane = threadIdx.x & 31;
    const int warp = (blockIdx.x * blockDim.x + threadIdx.x) >> 5;
    const int nwarps = (gridDim.x * blockDim.x) >> 5;
    for (int row = warp; row < n; row += nwarps) {
        float x0 = X[(size_t)row * 32 + lane];
        float a0 = 0.f, a1 = 0.f;
#pragma unroll
        for (int k = 0; k < 32; k++) {
            float xv = __shfl_sync(0xffffffffu, x0, k);
            a0 += xv * Ws[k * 64 + lane];
            a1 += xv * Ws[k * 64 + 32 + lane];
        }
        g_hW[(size_t)row * 64 + lane] = a0;
        g_hW[(size_t)row * 64 + 32 + lane] = a1;
    }
    // norm fill: warp per node, lanes stride the node's CSR slots.
    for (int node = warp; node < n; node += nwarps) {
        float dn = g_dinv[node];
        int s0 = g_rowptr[node], s1 = g_rowptr[node + 1];
        for (int i = s0 + lane; i < s1; i += 32)
            g_enorm[i] = g_dinv[g_esrc[i]] * dn;
    }
}

// Mid-layer GEMM: g_hW[n,64] = g_h[n,64] @ W[64,64]. Warp-per-row.
__global__ void gemm64_kernel(const float* __restrict__ W, int n) {
    __shared__ float Ws[64 * 64];
    for (int i = threadIdx.x; i < 64 * 64; i += blockDim.x) Ws[i] = W[i];
    __syncthreads();
    const int lane = threadIdx.x & 31;
    const int warp = (blockIdx.x * blockDim.x + threadIdx.x) >> 5;
    const int nwarps = (gridDim.x * blockDim.x) >> 5;
    for (int row = warp; row < n; row += nwarps) {
        float x0 = g_h[(size_t)row * 64 + lane];
        float x1 = g_h[(size_t)row * 64 + 32 + lane];
        float a0 = 0.f, a1 = 0.f;
#pragma unroll
        for (int k = 0; k < 32; k++) {
            float xv = __shfl_sync(0xffffffffu, x0, k);
            a0 += xv * Ws[k * 64 + lane];
            a1 += xv * Ws[k * 64 + 32 + lane];
        }
#pragma unroll
        for (int k = 0; k < 32; k++) {
            float xv = __shfl_sync(0xffffffffu, x1, k);
            a0 += xv * Ws[(k + 32) * 64 + lane];
            a1 += xv * Ws[(k + 32) * 64 + 32 + lane];
        }
        g_hW[(size_t)row * 64 + lane] = a0;
        g_hW[(size_t)row * 64 + 32 + lane] = a1;
    }
}

// ---------------------------------------------------------------------------
// Gather-only aggregation, 4-deep edge unroll:
//   g_h[i] = relu(sum_e norm_e*g_hW[src_e] + dinv_i^2*g_hW[i] + b)
__global__ void aggregate_kernel(const float* __restrict__ b, int n) {
    const int lane = threadIdx.x & 31;
    const int node = (blockIdx.x * blockDim.x + threadIdx.x) >> 5;
    if (node >= n) return;
    float dn = g_dinv[node];
    float self = dn * dn;
    float a0 = self * g_hW[(size_t)node * 64 + lane];
    float a1 = self * g_hW[(size_t)node * 64 + 32 + lane];
    int p = g_rowptr[node];
    const int e = g_rowptr[node + 1];
    const int m = p + ((e - p) & ~3);
    for (; p < m; p += 4) {
        int i0 = g_esrc[p],     i1 = g_esrc[p + 1];
        int i2 = g_esrc[p + 2], i3 = g_esrc[p + 3];
        float w0 = g_enorm[p],     w1 = g_enorm[p + 1];
        float w2 = g_enorm[p + 2], w3 = g_enorm[p + 3];
        const float* s0 = g_hW + (size_t)i0 * 64;
        const float* s1 = g_hW + (size_t)i1 * 64;
        const float* s2 = g_hW + (size_t)i2 * 64;
        const float* s3 = g_hW + (size_t)i3 * 64;
        float v00 = s0[lane], v01 = s0[32 + lane];
        float v10 = s1[lane], v11 = s1[32 + lane];
        float v20 = s2[lane], v21 = s2[32 + lane];
        float v30 = s3[lane], v31 = s3[32 + lane];
        a0 += w0 * v00; a1 += w0 * v01;
        a0 += w1 * v10; a1 += w1 * v11;
        a0 += w2 * v20; a1 += w2 * v21;
        a0 += w3 * v30; a1 += w3 * v31;
    }
    for (; p < e; p++) {
        float w = g_enorm[p];
        const float* s = g_hW + (size_t)g_esrc[p] * 64;
        a0 += w * s[lane];
        a1 += w * s[32 + lane];
    }
    a0 += b[lane];
    a1 += b[32 + lane];
    g_h[(size_t)node * 64 + lane] = fmaxf(a0, 0.f);
    g_h[(size_t)node * 64 + 32 + lane] = fmaxf(a1, 0.f);
}

// ---------------------------------------------------------------------------
__device__ __forceinline__ int lbound(const int* __restrict__ a, int n, int v) {
    int lo = 0, hi = n;
    while (lo < hi) {
        int m = (lo + hi) >> 1;
        if (a[m] < v) lo = m + 1; else hi = m;
    }
    return lo;
}

// Fused mean-pool + MLP head. One warp per graph (batch ids sorted).
__global__ void pool_mlp_kernel(const int* __restrict__ batch,
                                const float* __restrict__ lw1,
                                const float* __restrict__ lb1,
                                const float* __restrict__ lw2,
                                const float* __restrict__ lb2,
                                float* __restrict__ out, int n, int G) {
    const int lane = threadIdx.x & 31;
    const int g = (blockIdx.x * blockDim.x + threadIdx.x) >> 5;
    if (g >= G) return;
    int start = lbound(batch, n, g);
    int end   = lbound(batch, n, g + 1);
    float p0 = 0.f, p1 = 0.f;
    for (int i = start; i < end; i++) {
        p0 += g_h[(size_t)i * 64 + lane];
        p1 += g_h[(size_t)i * 64 + 32 + lane];
    }
    int cnt = end - start;
    float inv = 1.f / (float)(cnt > 0 ? cnt : 1);
    p0 *= inv; p1 *= inv;

    float a0 = lb1[lane], a1 = lb1[32 + lane];
#pragma unroll
    for (int k = 0; k < 32; k++) {
        float xv = __shfl_sync(0xffffffffu, p0, k);
        a0 += xv * lw1[k * 64 + lane];
        a1 += xv * lw1[k * 64 + 32 + lane];
    }
#pragma unroll
    for (int k = 0; k < 32; k++) {
        float xv = __shfl_sync(0xffffffffu, p1, k);
        a0 += xv * lw1[(k + 32) * 64 + lane];
        a1 += xv * lw1[(k + 32) * 64 + 32 + lane];
    }
    a0 = fmaxf(a0, 0.f);
    a1 = fmaxf(a1, 0.f);
    float o0 = a0 * lw2[lane * 2 + 0] + a1 * lw2[(lane + 32) * 2 + 0];
    float o1 = a0 * lw2[lane * 2 + 1] + a1 * lw2[(lane + 32) * 2 + 1];
#pragma unroll
    for (int off = 16; off; off >>= 1) {
        o0 += __shfl_down_sync(0xffffffffu, o0, off);
        o1 += __shfl_down_sync(0xffffffffu, o1, off);
    }
    if (lane == 0) {
        out[g * 2 + 0] = o0 + lb2[0];
        out[g * 2 + 1] = o1 + lb2[1];
    }
}

// ---------------------------------------------------------------------------
extern "C" void kernel_launch(void* const* d_in, const int* in_sizes, int n_in,
                              void* d_out, int out_size) {
    const float* x     = (const float*)d_in[0];
    const int*   ei    = (const int*)d_in[1];    // int64 ref -> int32 device
    const int*   batch = (const int*)d_in[2];
    const float* W1 = (const float*)d_in[3];
    const float* b1 = (const float*)d_in[4];
    const float* W2 = (const float*)d_in[5];
    const float* b2 = (const float*)d_in[6];
    const float* W3 = (const float*)d_in[7];
    const float* b3 = (const float*)d_in[8];
    const float* lw1 = (const float*)d_in[9];
    const float* lb1 = (const float*)d_in[10];
    const float* lw2 = (const float*)d_in[11];
    const float* lb2 = (const float*)d_in[12];
    float* out = (float*)d_out;

    const int N = in_sizes[0] / 32;
    const int E = in_sizes[1] / 2;
    const int G = out_size / 2;

    const int T = 256;
    const int nb = (N + SCAN_B - 1) / SCAN_B;   // <= NB_MAX
    const int e4 = (E + 3) / 4;
    const int work_blocks = 592;                 // persistent-style loops
    const int agg_blocks = (N * 32 + T - 1) / T;

    // --- CSR build (4 launches) ---
    hist_kernel<<<(e4 + T - 1) / T, T>>>(ei, E);
    scanA_kernel<<<nb, SCAN_B>>>(N, nb);
    scanC_kernel<<<nb, SCAN_B>>>(N);
    scatter_kernel<<<(e4 + T - 1) / T, T>>>(ei, E);

    // --- Layers (6 launches; launch #6 overall = aggregate -> ncu target) ---
    gemm1_norm_kernel<<<work_blocks, T>>>(x, W1, N);
    aggregate_kernel<<<agg_blocks, T>>>(b1, N);
    gemm64_kernel<<<work_blocks, T>>>(W2, N);
    aggregate_kernel<<<agg_blocks, T>>>(b2, N);
    gemm64_kernel<<<work_blocks, T>>>(W3, N);
    aggregate_kernel<<<agg_blocks, T>>>(b3, N);

    // --- Fused pool + MLP head (1 launch) ---
    pool_mlp_kernel<<<(G * 32 + T - 1) / T, T>>>(batch, lw1, lb1, lw2, lb2,
                                                 out, N, G);
}

// round 7
// speedup vs baseline: 1.1399x; 1.0640x over previous
#include <cuda_runtime.h>
#include <cuda_fp16.h>
#include <cuda_bf16.h>

// GCN: 3x (h = relu(A_norm @ (h @ W) + b)) -> global mean pool -> MLP.
// 9 launches: hist(+rank), scan(fused, spin-synced), scatter(NO atomics),
// gemm1+norm-fill, [agg, gemm]x2, agg3, pool+mlp.
// hW stored as fp16 (one 128B line per row) -> aggregate gather bytes halved;
// accumulation in fp32. Gather-only aggregation (no float atomics).
// Feature mapping everywhere: lane l owns features (2l, 2l+1).

#define NMAX 50000
#define EMAX 800000
#define GMAX 2048
#define SCAN_B 1024
#define NB_MAX 64

__device__ __half2 g_hW16[NMAX * 32];  // X @ W scratch, fp16 pairs (agg input)
__device__ float2  g_h2[NMAX * 32];    // activations fp32 pairs (gemm input)
__device__ float   g_dinv[NMAX];       // 1/sqrt(deg+1)
__device__ int     g_deg[NMAX];        // histogram (re-zeroed every run)
__device__ int     g_rowptr[NMAX + 1]; // CSR row pointers (by dst)
__device__ int     g_rank[EMAX];       // per-edge within-node rank (from hist)
__device__ int     g_esrc[EMAX];       // CSR edge sources
__device__ float   g_enorm[EMAX];      // CSR edge norms dinv[s]*dinv[d]
__device__ int     g_bsum[NB_MAX];     // scan block sums
__device__ int     g_tick1, g_tick2;   // scan spin tickets (self-resetting)

// ---------------------------------------------------------------------------
// Histogram of dst; the atomic's return value is the edge's rank (stored).
__global__ void hist_kernel(const int* __restrict__ ei, int E) {
    int base = (blockIdx.x * blockDim.x + threadIdx.x) * 4;
    if ((E & 3) == 0) {
        if (base < E) {
            int4 d = *reinterpret_cast<const int4*>(ei + E + base);
            int4 r;
            r.x = atomicAdd(&g_deg[d.x], 1);
            r.y = atomicAdd(&g_deg[d.y], 1);
            r.z = atomicAdd(&g_deg[d.z], 1);
            r.w = atomicAdd(&g_deg[d.w], 1);
            *reinterpret_cast<int4*>(g_rank + base) = r;
        }
    } else {
#pragma unroll
        for (int j = 0; j < 4; j++)
            if (base + j < E)
                g_rank[base + j] = atomicAdd(&g_deg[ei[E + base + j]], 1);
    }
}

// Fused scan: per-block reduce -> g_bsum, spin until all posted, then each
// block sums its prefix and writes rowptr/dinv, zeroes deg. All nb (<=49)
// blocks are chip-resident so the spin cannot deadlock. Tickets self-reset.
__global__ void scan_kernel(int n, int nb) {
    __shared__ int ws[32];
    __shared__ int blockoff;
    const int lane = threadIdx.x & 31, wid = threadIdx.x >> 5;
    int idx = blockIdx.x * SCAN_B + threadIdx.x;
    int v = (idx < n) ? g_deg[idx] : 0;
    int sc = v;
#pragma unroll
    for (int off = 1; off < 32; off <<= 1) {
        int u = __shfl_up_sync(0xffffffffu, sc, off);
        if (lane >= off) sc += u;
    }
    if (lane == 31) ws[wid] = sc;
    __syncthreads();
    if (wid == 0) {
        int s = ws[lane];
#pragma unroll
        for (int off = 1; off < 32; off <<= 1) {
            int u = __shfl_up_sync(0xffffffffu, s, off);
            if (lane >= off) s += u;
        }
        ws[lane] = s;
    }
    __syncthreads();
    if (threadIdx.x == 0) {
        g_bsum[blockIdx.x] = ws[31];           // block total
        __threadfence();
        atomicAdd(&g_tick1, 1);
        while (*((volatile int*)&g_tick1) < nb) {}   // wait for all posts
        int run = 0;
        for (int j = 0; j < blockIdx.x; j++)
            run += ((volatile int*)g_bsum)[j];
        blockoff = run;
    }
    __syncthreads();
    int ex = blockoff + (wid ? ws[wid - 1] : 0) + sc - v;
    if (idx < n) {
        g_rowptr[idx] = ex;
        g_dinv[idx] = rsqrtf((float)(v + 1));   // +1 self loop
        g_deg[idx] = 0;                          // ready for next replay
        if (idx == n - 1) g_rowptr[n] = ex + v;
    }
    __syncthreads();
    if (threadIdx.x == 0) {
        int t = atomicAdd(&g_tick2, 1);
        if (t == nb - 1) { g_tick1 = 0; g_tick2 = 0; __threadfence(); }
    }
}

// Scatter with NO atomics: pos = rowptr[dst] + rank.
__global__ void scatter_kernel(const int* __restrict__ ei, int E) {
    int base = (blockIdx.x * blockDim.x + threadIdx.x) * 4;
    if ((E & 3) == 0) {
        if (base < E) {
            int4 s4 = *reinterpret_cast<const int4*>(ei + base);
            int4 d4 = *reinterpret_cast<const int4*>(ei + E + base);
            int4 r4 = *reinterpret_cast<const int4*>(g_rank + base);
            g_esrc[g_rowptr[d4.x] + r4.x] = s4.x;
            g_esrc[g_rowptr[d4.y] + r4.y] = s4.y;
            g_esrc[g_rowptr[d4.z] + r4.z] = s4.z;
            g_esrc[g_rowptr[d4.w] + r4.w] = s4.w;
        }
    } else {
#pragma unroll
        for (int j = 0; j < 4; j++) {
            if (base + j < E) {
                int s = ei[base + j], d = ei[E + base + j];
                g_esrc[g_rowptr[d] + g_rank[base + j]] = s;
            }
        }
    }
}

// ---------------------------------------------------------------------------
// Layer-1 GEMM: g_hW16[n] = fp16(X[n,32] @ W1[32,64]) + edge norm fill.
// Lane l computes features (2l, 2l+1).
__global__ void gemm1_norm_kernel(const float* __restrict__ X,
                                  const float* __restrict__ W, int n) {
    __shared__ float2 Ws[32 * 32];   // Ws[k*32+l] = (W[k][2l], W[k][2l+1])
    for (int i = threadIdx.x; i < 32 * 32; i += blockDim.x)
        Ws[i] = reinterpret_cast<const float2*>(W)[i];
    __syncthreads();
    const int lane = threadIdx.x & 31;
    const int warp = (blockIdx.x * blockDim.x + threadIdx.x) >> 5;
    const int nwarps = (gridDim.x * blockDim.x) >> 5;
    for (int row = warp; row < n; row += nwarps) {
        float x0 = X[(size_t)row * 32 + lane];
        float ax = 0.f, ay = 0.f;
#pragma unroll
        for (int k = 0; k < 32; k++) {
            float xv = __shfl_sync(0xffffffffu, x0, k);
            float2 w = Ws[k * 32 + lane];
            ax += xv * w.x;
            ay += xv * w.y;
        }
        g_hW16[(size_t)row * 32 + lane] = __floats2half2_rn(ax, ay);
    }
    // norm fill: warp per node, lanes stride the node's CSR slots.
    for (int node = warp; node < n; node += nwarps) {
        float dn = g_dinv[node];
        int s0 = g_rowptr[node], s1 = g_rowptr[node + 1];
        for (int i = s0 + lane; i < s1; i += 32)
            g_enorm[i] = g_dinv[g_esrc[i]] * dn;
    }
}

// Mid-layer GEMM: g_hW16[n] = fp16(g_h2[n,64] @ W[64,64]). Warp-per-row.
__global__ void gemm64_kernel(const float* __restrict__ W, int n) {
    __shared__ float2 Ws[64 * 32];   // Ws[r*32+l] = (W[r][2l], W[r][2l+1])
    for (int i = threadIdx.x; i < 64 * 32; i += blockDim.x)
        Ws[i] = reinterpret_cast<const float2*>(W)[i];
    __syncthreads();
    const int lane = threadIdx.x & 31;
    const int warp = (blockIdx.x * blockDim.x + threadIdx.x) >> 5;
    const int nwarps = (gridDim.x * blockDim.x) >> 5;
    for (int row = warp; row < n; row += nwarps) {
        float2 xr = g_h2[(size_t)row * 32 + lane];   // features 2l, 2l+1
        float ax = 0.f, ay = 0.f;
#pragma unroll
        for (int k = 0; k < 32; k++) {
            float xk0 = __shfl_sync(0xffffffffu, xr.x, k);  // feature 2k
            float xk1 = __shfl_sync(0xffffffffu, xr.y, k);  // feature 2k+1
            float2 w0 = Ws[(2 * k) * 32 + lane];
            float2 w1 = Ws[(2 * k + 1) * 32 + lane];
            ax += xk0 * w0.x + xk1 * w1.x;
            ay += xk0 * w0.y + xk1 * w1.y;
        }
        g_hW16[(size_t)row * 32 + lane] = __floats2half2_rn(ax, ay);
    }
}

// ---------------------------------------------------------------------------
// Gather-only aggregation (fp16 gathers, fp32 accumulate), 4-deep unroll:
//   g_h2[i] = relu(sum_e norm_e*hW16[src_e] + dinv_i^2*hW16[i] + b)
__global__ void aggregate_kernel(const float* __restrict__ b, int n) {
    const int lane = threadIdx.x & 31;
    const int node = (blockIdx.x * blockDim.x + threadIdx.x) >> 5;
    if (node >= n) return;
    float dn = g_dinv[node];
    float self = dn * dn;
    float2 sv = __half22float2(g_hW16[(size_t)node * 32 + lane]);
    float ax = self * sv.x, ay = self * sv.y;
    int p = g_rowptr[node];
    const int e = g_rowptr[node + 1];
    const int m = p + ((e - p) & ~3);
    for (; p < m; p += 4) {
        int i0 = g_esrc[p],     i1 = g_esrc[p + 1];
        int i2 = g_esrc[p + 2], i3 = g_esrc[p + 3];
        float w0 = g_enorm[p],     w1 = g_enorm[p + 1];
        float w2 = g_enorm[p + 2], w3 = g_enorm[p + 3];
        float2 v0 = __half22float2(g_hW16[(size_t)i0 * 32 + lane]);
        float2 v1 = __half22float2(g_hW16[(size_t)i1 * 32 + lane]);
        float2 v2 = __half22float2(g_hW16[(size_t)i2 * 32 + lane]);
        float2 v3 = __half22float2(g_hW16[(size_t)i3 * 32 + lane]);
        ax += w0 * v0.x; ay += w0 * v0.y;
        ax += w1 * v1.x; ay += w1 * v1.y;
        ax += w2 * v2.x; ay += w2 * v2.y;
        ax += w3 * v3.x; ay += w3 * v3.y;
    }
    for (; p < e; p++) {
        float w = g_enorm[p];
        float2 v = __half22float2(g_hW16[(size_t)g_esrc[p] * 32 + lane]);
        ax += w * v.x;
        ay += w * v.y;
    }
    float2 bb = reinterpret_cast<const float2*>(b)[lane];
    g_h2[(size_t)node * 32 + lane] =
        make_float2(fmaxf(ax + bb.x, 0.f), fmaxf(ay + bb.y, 0.f));
}

// ---------------------------------------------------------------------------
__device__ __forceinline__ int lbound(const int* __restrict__ a, int n, int v) {
    int lo = 0, hi = n;
    while (lo < hi) {
        int m = (lo + hi) >> 1;
        if (a[m] < v) lo = m + 1; else hi = m;
    }
    return lo;
}

// Fused mean-pool + MLP head. One warp per graph (batch ids sorted).
__global__ void pool_mlp_kernel(const int* __restrict__ batch,
                                const float* __restrict__ lw1,
                                const float* __restrict__ lb1,
                                const float* __restrict__ lw2,
                                const float* __restrict__ lb2,
                                float* __restrict__ out, int n, int G) {
    __shared__ float2 Ws[64 * 32];   // lw1 pairs
    for (int i = threadIdx.x; i < 64 * 32; i += blockDim.x)
        Ws[i] = reinterpret_cast<const float2*>(lw1)[i];
    __syncthreads();
    const int lane = threadIdx.x & 31;
    const int g = (blockIdx.x * blockDim.x + threadIdx.x) >> 5;
    if (g >= G) return;
    int start = lbound(batch, n, g);
    int end   = lbound(batch, n, g + 1);
    float px = 0.f, py = 0.f;
    for (int i = start; i < end; i++) {
        float2 v = g_h2[(size_t)i * 32 + lane];
        px += v.x; py += v.y;
    }
    int cnt = end - start;
    float inv = 1.f / (float)(cnt > 0 ? cnt : 1);
    px *= inv; py *= inv;

    float2 lb = reinterpret_cast<const float2*>(lb1)[lane];
    float ax = lb.x, ay = lb.y;                 // hidden 2l, 2l+1
#pragma unroll
    for (int k = 0; k < 32; k++) {
        float pk0 = __shfl_sync(0xffffffffu, px, k);   // pooled feat 2k
        float pk1 = __shfl_sync(0xffffffffu, py, k);   // pooled feat 2k+1
        float2 w0 = Ws[(2 * k) * 32 + lane];
        float2 w1 = Ws[(2 * k + 1) * 32 + lane];
        ax += pk0 * w0.x + pk1 * w1.x;
        ay += pk0 * w0.y + pk1 * w1.y;
    }
    ax = fmaxf(ax, 0.f);
    ay = fmaxf(ay, 0.f);
    // lw2 is [64][2]: float4 at lane l = (lw2[2l][0], lw2[2l][1],
    //                                     lw2[2l+1][0], lw2[2l+1][1])
    float4 w2 = reinterpret_cast<const float4*>(lw2)[lane];
    float o0 = ax * w2.x + ay * w2.z;
    float o1 = ax * w2.y + ay * w2.w;
#pragma unroll
    for (int off = 16; off; off >>= 1) {
        o0 += __shfl_down_sync(0xffffffffu, o0, off);
        o1 += __shfl_down_sync(0xffffffffu, o1, off);
    }
    if (lane == 0) {
        out[g * 2 + 0] = o0 + lb2[0];
        out[g * 2 + 1] = o1 + lb2[1];
    }
}

// ---------------------------------------------------------------------------
extern "C" void kernel_launch(void* const* d_in, const int* in_sizes, int n_in,
                              void* d_out, int out_size) {
    const float* x     = (const float*)d_in[0];
    const int*   ei    = (const int*)d_in[1];    // int64 ref -> int32 device
    const int*   batch = (const int*)d_in[2];
    const float* W1 = (const float*)d_in[3];
    const float* b1 = (const float*)d_in[4];
    const float* W2 = (const float*)d_in[5];
    const float* b2 = (const float*)d_in[6];
    const float* W3 = (const float*)d_in[7];
    const float* b3 = (const float*)d_in[8];
    const float* lw1 = (const float*)d_in[9];
    const float* lb1 = (const float*)d_in[10];
    const float* lw2 = (const float*)d_in[11];
    const float* lb2 = (const float*)d_in[12];
    float* out = (float*)d_out;

    const int N = in_sizes[0] / 32;
    const int E = in_sizes[1] / 2;
    const int G = out_size / 2;

    const int T = 256;
    const int nb = (N + SCAN_B - 1) / SCAN_B;   // <= NB_MAX, all resident
    const int e4 = (E + 3) / 4;
    const int work_blocks = 592;
    const int agg_blocks = (N * 32 + T - 1) / T;

    // --- CSR build (3 launches) ---
    hist_kernel<<<(e4 + T - 1) / T, T>>>(ei, E);
    scan_kernel<<<nb, SCAN_B>>>(N, nb);
    scatter_kernel<<<(e4 + T - 1) / T, T>>>(ei, E);

    // --- Layers (6 launches) ---
    gemm1_norm_kernel<<<work_blocks, T>>>(x, W1, N);
    aggregate_kernel<<<agg_blocks, T>>>(b1, N);
    gemm64_kernel<<<work_blocks, T>>>(W2, N);
    aggregate_kernel<<<agg_blocks, T>>>(b2, N);
    gemm64_kernel<<<work_blocks, T>>>(W3, N);
    aggregate_kernel<<<agg_blocks, T>>>(b3, N);

    // --- Fused pool + MLP head (1 launch) ---
    pool_mlp_kernel<<<(G * 32 + T - 1) / T, T>>>(batch, lw1, lb1, lw2, lb2,
                                                 out, N, G);
}